// round 6
// baseline (speedup 1.0000x reference)
#include <cuda_runtime.h>
#include <cstdint>
#include <math.h>

// ---------------- problem constants ----------------
#define N_TOK 4096
#define DIM   1024
#define FF    4096
#define NE    8
#define TEMP  0.9f
#define EPS   1e-5f
#define PADMAX 9216

// ---------------- static device scratch ----------------
__device__ float g_Xe[(size_t)PADMAX * DIM];     // tf32-rounded gathered X
__device__ float g_H [(size_t)PADMAX * FF];      // tf32-rounded gelu acts
__device__ float g_Y [(size_t)PADMAX * DIM];     // fp32 expert outputs
__device__ float g_w1c[(size_t)NE * DIM * FF];   // tf32-rounded w1
__device__ float g_w2c[(size_t)NE * FF * DIM];   // tf32-rounded w2
__device__ int   g_e0[N_TOK], g_e1[N_TOK];
__device__ float g_p0[N_TOK], g_p1[N_TOK];
__device__ int   g_pp0[N_TOK], g_pp1[N_TOK];
__device__ int   g_counts[NE], g_poff[NE], g_cursor[NE];
__device__ int   g_rowtok[PADMAX];

// ---------------- helpers ----------------
__device__ __forceinline__ uint32_t smem_u32(const void* p) {
    uint32_t a;
    asm("{ .reg .u64 t; cvta.to.shared.u64 t, %1; cvt.u32.u64 %0, t; }" : "=r"(a) : "l"(p));
    return a;
}
__device__ __forceinline__ void cp_async16(uint32_t dst, const void* src) {
    asm volatile("cp.async.cg.shared.global [%0], [%1], 16;" :: "r"(dst), "l"(src));
}
__device__ __forceinline__ uint32_t f2tf32(float f) {
    uint32_t u;
    asm("cvt.rna.tf32.f32 %0, %1;" : "=r"(u) : "f"(f));
    return u;
}
__device__ __forceinline__ float round_tf32(float f) {
    return __uint_as_float(f2tf32(f));
}
__device__ __forceinline__ void mma_tf32(float* c, const uint32_t* a, const uint32_t* b) {
    asm volatile(
        "mma.sync.aligned.m16n8k8.row.col.f32.tf32.tf32.f32 "
        "{%0,%1,%2,%3}, {%4,%5,%6,%7}, {%8,%9}, {%0,%1,%2,%3};"
        : "+f"(c[0]), "+f"(c[1]), "+f"(c[2]), "+f"(c[3])
        : "r"(a[0]), "r"(a[1]), "r"(a[2]), "r"(a[3]), "r"(b[0]), "r"(b[1]));
}
__device__ __forceinline__ float warp_sum(float v) {
#pragma unroll
    for (int o = 16; o > 0; o >>= 1) v += __shfl_xor_sync(0xffffffffu, v, o);
    return v;
}

// ---------------- weight pre-rounding ----------------
__global__ __launch_bounds__(256)
void convw_kernel(const float* __restrict__ w1, const float* __restrict__ w2) {
    const size_t total4 = (size_t)NE * DIM * FF / 4;
    size_t i = (size_t)blockIdx.x * 256 + threadIdx.x;
    const float4* s1 = reinterpret_cast<const float4*>(w1);
    const float4* s2 = reinterpret_cast<const float4*>(w2);
    float4* d1 = reinterpret_cast<float4*>(g_w1c);
    float4* d2 = reinterpret_cast<float4*>(g_w2c);
    for (size_t j = i; j < total4; j += (size_t)gridDim.x * 256) {
        float4 v = s1[j];
        d1[j] = make_float4(round_tf32(v.x), round_tf32(v.y), round_tf32(v.z), round_tf32(v.w));
        float4 u = s2[j];
        d2[j] = make_float4(round_tf32(u.x), round_tf32(u.y), round_tf32(u.z), round_tf32(u.w));
    }
}

// ---------------- small kernels ----------------
__global__ void zero_kernel() {
    if (threadIdx.x < NE) g_counts[threadIdx.x] = 0;
}

__global__ void gate_kernel(const float* __restrict__ x,
                            const float* __restrict__ gw,
                            const float* __restrict__ gb) {
    int warp = threadIdx.x >> 5, lane = threadIdx.x & 31;
    int t = blockIdx.x * 4 + warp;
    if (t >= N_TOK) return;
    float acc[NE];
#pragma unroll
    for (int e = 0; e < NE; e++) acc[e] = 0.f;
    const float* xr = x + (size_t)t * DIM;
    for (int d = lane; d < DIM; d += 32) {
        float xv = xr[d];
        const float4* g4 = reinterpret_cast<const float4*>(gw + (size_t)d * NE);
        float4 a = g4[0], b = g4[1];
        acc[0] += xv * a.x; acc[1] += xv * a.y; acc[2] += xv * a.z; acc[3] += xv * a.w;
        acc[4] += xv * b.x; acc[5] += xv * b.y; acc[6] += xv * b.z; acc[7] += xv * b.w;
    }
#pragma unroll
    for (int e = 0; e < NE; e++) acc[e] = warp_sum(acc[e]);
    if (lane == 0) {
        float lg[NE];
#pragma unroll
        for (int e = 0; e < NE; e++) lg[e] = (acc[e] + gb[e]) / TEMP;
        int i0 = 0;
#pragma unroll
        for (int e = 1; e < NE; e++) if (lg[e] > lg[i0]) i0 = e;
        int i1 = (i0 == 0) ? 1 : 0;
#pragma unroll
        for (int e = 0; e < NE; e++)
            if (e != i0 && lg[e] > lg[i1]) i1 = e;
        float ev = expf(lg[i1] - lg[i0]);
        float s = 1.f + ev;
        g_e0[t] = i0; g_e1[t] = i1;
        g_p0[t] = 1.f / s; g_p1[t] = ev / s;
        atomicAdd(&g_counts[i0], 1);
        atomicAdd(&g_counts[i1], 1);
    }
}

__global__ void prefix_kernel() {
    if (threadIdx.x == 0) {
        int s = 0;
        for (int e = 0; e < NE; e++) {
            g_poff[e] = s;
            s += ((g_counts[e] + 127) / 128) * 128;
            g_cursor[e] = 0;
        }
    }
}

__global__ void assign_kernel() {
    int t = blockIdx.x * 256 + threadIdx.x;
    if (t >= N_TOK) return;
    int e0 = g_e0[t], e1 = g_e1[t];
    int p = g_poff[e0] + atomicAdd(&g_cursor[e0], 1);
    g_rowtok[p] = t; g_pp0[t] = p;
    int q = g_poff[e1] + atomicAdd(&g_cursor[e1], 1);
    g_rowtok[q] = t; g_pp1[t] = q;
}

// gather + tf32-round selected token rows into padded per-expert slabs
__global__ void gather_kernel(const float* __restrict__ x) {
    int e  = blockIdx.y;
    int mt = blockIdx.x;
    int cnt = g_counts[e];
    if (mt * 128 >= cnt) return;
    int base = g_poff[e] + mt * 128;
    int tid = threadIdx.x;
    const float4* x4 = reinterpret_cast<const float4*>(x);
    float4* o4 = reinterpret_cast<float4*>(g_Xe);
#pragma unroll 4
    for (int i = 0; i < 128; i++) {
        if (mt * 128 + i < cnt) {
            int tok = g_rowtok[base + i];
            float4 v = x4[(size_t)tok * (DIM / 4) + tid];
            o4[(size_t)(base + i) * (DIM / 4) + tid] =
                make_float4(round_tf32(v.x), round_tf32(v.y), round_tf32(v.z), round_tf32(v.w));
        }
    }
}

// ---------------- tf32 mma.sync GEMM ----------------
// CTA tile 128x128, BK=32, 256 threads = 8 warps (4x2), warp tile 32x64.
// Inputs are pre-rounded tf32 bit patterns: no cvt in the mainloop.
// Weight array selected by template flag INSIDE device code (device symbols
// are not valid host-side pointers).
#define A_STG (128 * 36)
#define B_STG (32 * 132)
#define SMEM_FFN_BYTES ((2 * A_STG + 2 * B_STG) * 4)

template<int K, int NF, bool GELU>
__global__ __launch_bounds__(256, 2)
void ffn_mma_kernel(const float* __restrict__ bias_in) {
    int e = blockIdx.z;
    int cnt = g_counts[e];
    int mt = blockIdx.y;
    if (mt * 128 >= cnt) return;
    int m0 = g_poff[e] + mt * 128;
    int n0 = blockIdx.x * 128;

    const float* W = GELU ? g_w1c : g_w2c;
    const float* Abase = (GELU ? g_Xe : g_H) + (size_t)m0 * K;
    const float* Bbase = W + (size_t)e * K * NF + n0;
    float* Cout = GELU ? g_H : g_Y;
    const float* bias = bias_in + (size_t)e * NF + n0;

    extern __shared__ float sm[];
    float* Asm = sm;
    float* Bsm = sm + 2 * A_STG;
    uint32_t sA32 = smem_u32(Asm), sB32 = smem_u32(Bsm);

    int tid = threadIdx.x, wid = tid >> 5, lane = tid & 31;
    int warp_m = wid & 3, warp_n = wid >> 2;
    int group = lane >> 2, tig = lane & 3;

    auto load_stage = [&](int kt, int s) {
        int k0 = kt * 32;
        uint32_t aD = sA32 + s * (A_STG * 4);
        uint32_t bD = sB32 + s * (B_STG * 4);
#pragma unroll
        for (int i = 0; i < 4; i++) {
            int idx = tid + i * 256;
            int row = idx >> 3, c8 = idx & 7;
            cp_async16(aD + row * 144 + c8 * 16, Abase + (size_t)row * K + k0 + c8 * 4);
        }
#pragma unroll
        for (int i = 0; i < 4; i++) {
            int idx = tid + i * 256;
            int kk = idx >> 5, c16 = idx & 31;
            cp_async16(bD + kk * 528 + c16 * 16, Bbase + (size_t)(k0 + kk) * NF + c16 * 4);
        }
        asm volatile("cp.async.commit_group;");
    };

    float acc[2][8][4];
#pragma unroll
    for (int i = 0; i < 2; i++)
#pragma unroll
        for (int j = 0; j < 8; j++)
#pragma unroll
            for (int q = 0; q < 4; q++) acc[i][j][q] = 0.f;

    const int ktiles = K / 32;
    load_stage(0, 0);

    for (int kt = 0; kt < ktiles; kt++) {
        int s = kt & 1;
        if (kt + 1 < ktiles) {
            load_stage(kt + 1, s ^ 1);
            asm volatile("cp.async.wait_group 1;" ::: "memory");
        } else {
            asm volatile("cp.async.wait_group 0;" ::: "memory");
        }
        __syncthreads();

        const uint32_t* Ab = reinterpret_cast<const uint32_t*>(Asm + s * A_STG);
        const uint32_t* Bb = reinterpret_cast<const uint32_t*>(Bsm + s * B_STG);
#pragma unroll
        for (int ks = 0; ks < 4; ks++) {
            int kb = ks * 8;
            uint32_t a[2][4], b[8][2];
#pragma unroll
            for (int m = 0; m < 2; m++) {
                int r = warp_m * 32 + m * 16 + group;
                a[m][0] = Ab[r * 36 + kb + tig];
                a[m][1] = Ab[(r + 8) * 36 + kb + tig];
                a[m][2] = Ab[r * 36 + kb + tig + 4];
                a[m][3] = Ab[(r + 8) * 36 + kb + tig + 4];
            }
#pragma unroll
            for (int n = 0; n < 8; n++) {
                int c = warp_n * 64 + n * 8 + group;
                b[n][0] = Bb[(kb + tig) * 132 + c];
                b[n][1] = Bb[(kb + tig + 4) * 132 + c];
            }
#pragma unroll
            for (int m = 0; m < 2; m++)
#pragma unroll
                for (int n = 0; n < 8; n++)
                    mma_tf32(acc[m][n], a[m], b[n]);
        }
        __syncthreads();
    }

    // epilogue: bias (+gelu) and store; GEMM1 output is tf32-rounded for GEMM2
#pragma unroll
    for (int m = 0; m < 2; m++) {
        int r0 = m0 + warp_m * 32 + m * 16 + group;
#pragma unroll
        for (int n = 0; n < 8; n++) {
            int c = warp_n * 64 + n * 8 + tig * 2;
            float bv0 = bias[c], bv1 = bias[c + 1];
#pragma unroll
            for (int h = 0; h < 2; h++) {
                float v0 = acc[m][n][h * 2 + 0] + bv0;
                float v1 = acc[m][n][h * 2 + 1] + bv1;
                if (GELU) {
                    v0 = 0.5f * v0 * (1.f + erff(v0 * 0.70710678118654752f));
                    v1 = 0.5f * v1 * (1.f + erff(v1 * 0.70710678118654752f));
                    v0 = round_tf32(v0);
                    v1 = round_tf32(v1);
                }
                *reinterpret_cast<float2*>(Cout + (size_t)(r0 + h * 8) * NF + n0 + c) =
                    make_float2(v0, v1);
            }
        }
    }
}

// ---------------- combine + LayerNorm ----------------
__global__ void ln_kernel(const float* __restrict__ ln_g,
                          const float* __restrict__ ln_b,
                          float* __restrict__ out) {
    int t = blockIdx.x;
    __shared__ float sv[DIM];
    __shared__ float rs[8], rq[8];
    int tid = threadIdx.x;
    float p0 = g_p0[t], p1 = g_p1[t];
    const float* ya = g_Y + (size_t)g_pp0[t] * DIM;
    const float* yb = g_Y + (size_t)g_pp1[t] * DIM;
    float lsum = 0.f, lsq = 0.f;
    for (int d = tid; d < DIM; d += 256) {
        float v = p0 * ya[d] + p1 * yb[d];
        sv[d] = v;
        lsum += v; lsq += v * v;
    }
    lsum = warp_sum(lsum); lsq = warp_sum(lsq);
    int lane = tid & 31, wid = tid >> 5;
    if (lane == 0) { rs[wid] = lsum; rq[wid] = lsq; }
    __syncthreads();
    if (tid == 0) {
        float s = 0.f, q = 0.f;
#pragma unroll
        for (int w = 0; w < 8; w++) { s += rs[w]; q += rq[w]; }
        rs[0] = s; rq[0] = q;
    }
    __syncthreads();
    float mu  = rs[0] / DIM;
    float var = rq[0] / DIM - mu * mu;
    float inv = rsqrtf(var + EPS);
    float* outr = out + (size_t)t * DIM;
    for (int d = tid; d < DIM; d += 256)
        outr[d] = (sv[d] - mu) * inv * ln_g[d] + ln_b[d];
}

// ---------------- launch ----------------
extern "C" void kernel_launch(void* const* d_in, const int* in_sizes, int n_in,
                              void* d_out, int out_size) {
    const float* x      = (const float*)d_in[0];
    const float* gate_w = (const float*)d_in[1];
    const float* gate_b = (const float*)d_in[2];
    const float* w1     = (const float*)d_in[3];
    const float* b1     = (const float*)d_in[4];
    const float* w2     = (const float*)d_in[5];
    const float* b2     = (const float*)d_in[6];
    const float* ln_g   = (const float*)d_in[7];
    const float* ln_b   = (const float*)d_in[8];
    float* out = (float*)d_out;

    cudaFuncSetAttribute(ffn_mma_kernel<DIM, FF, true>,
                         cudaFuncAttributeMaxDynamicSharedMemorySize, SMEM_FFN_BYTES);
    cudaFuncSetAttribute(ffn_mma_kernel<FF, DIM, false>,
                         cudaFuncAttributeMaxDynamicSharedMemorySize, SMEM_FFN_BYTES);

    zero_kernel<<<1, 32>>>();
    convw_kernel<<<8192, 256>>>(w1, w2);
    gate_kernel<<<N_TOK / 4, 128>>>(x, gate_w, gate_b);
    prefix_kernel<<<1, 32>>>();
    assign_kernel<<<N_TOK / 256, 256>>>();
    gather_kernel<<<dim3(32, NE), 256>>>(x);
    ffn_mma_kernel<DIM, FF, true ><<<dim3(FF / 128, 32, NE), 256, SMEM_FFN_BYTES>>>(b1);
    ffn_mma_kernel<FF, DIM, false><<<dim3(DIM / 128, 32, NE), 256, SMEM_FFN_BYTES>>>(b2);
    ln_kernel<<<N_TOK, 256>>>(ln_g, ln_b, out);
}

// round 7
// speedup vs baseline: 1.1652x; 1.1652x over previous
#include <cuda_runtime.h>
#include <cstdint>
#include <math.h>

// ---------------- problem constants ----------------
#define N_TOK 4096
#define DIM   1024
#define FF    4096
#define NE    8
#define TEMP  0.9f
#define EPS   1e-5f
#define PADMAX 9216

// ---------------- static device scratch ----------------
__device__ float g_Xe[(size_t)PADMAX * DIM];     // tf32-rounded gathered X
__device__ float g_H [(size_t)PADMAX * FF];      // tf32-rounded gelu acts
__device__ float g_Y [(size_t)PADMAX * DIM];     // fp32 expert outputs
__device__ int   g_e0[N_TOK], g_e1[N_TOK];
__device__ float g_p0[N_TOK], g_p1[N_TOK];
__device__ int   g_pp0[N_TOK], g_pp1[N_TOK];
__device__ int   g_counts[NE], g_poff[NE], g_cursor[NE];
__device__ int   g_rowtok[PADMAX];

// ---------------- helpers ----------------
__device__ __forceinline__ uint32_t smem_u32(const void* p) {
    uint32_t a;
    asm("{ .reg .u64 t; cvta.to.shared.u64 t, %1; cvt.u32.u64 %0, t; }" : "=r"(a) : "l"(p));
    return a;
}
__device__ __forceinline__ void cp_async16(uint32_t dst, const void* src) {
    asm volatile("cp.async.cg.shared.global [%0], [%1], 16;" :: "r"(dst), "l"(src));
}
__device__ __forceinline__ uint32_t f2tf32(float f) {
    uint32_t u;
    asm("cvt.rna.tf32.f32 %0, %1;" : "=r"(u) : "f"(f));
    return u;
}
__device__ __forceinline__ float round_tf32(float f) {
    return __uint_as_float(f2tf32(f));
}
__device__ __forceinline__ void mma_tf32(float* c, const uint32_t* a, const uint32_t* b) {
    asm volatile(
        "mma.sync.aligned.m16n8k8.row.col.f32.tf32.tf32.f32 "
        "{%0,%1,%2,%3}, {%4,%5,%6,%7}, {%8,%9}, {%0,%1,%2,%3};"
        : "+f"(c[0]), "+f"(c[1]), "+f"(c[2]), "+f"(c[3])
        : "r"(a[0]), "r"(a[1]), "r"(a[2]), "r"(a[3]), "r"(b[0]), "r"(b[1]));
}
__device__ __forceinline__ float warp_sum(float v) {
#pragma unroll
    for (int o = 16; o > 0; o >>= 1) v += __shfl_xor_sync(0xffffffffu, v, o);
    return v;
}

// ---------------- small kernels ----------------
__global__ void zero_kernel() {
    if (threadIdx.x < NE) g_counts[threadIdx.x] = 0;
}

__global__ void gate_kernel(const float* __restrict__ x,
                            const float* __restrict__ gw,
                            const float* __restrict__ gb) {
    int warp = threadIdx.x >> 5, lane = threadIdx.x & 31;
    int t = blockIdx.x * 4 + warp;
    if (t >= N_TOK) return;
    float acc[NE];
#pragma unroll
    for (int e = 0; e < NE; e++) acc[e] = 0.f;
    const float* xr = x + (size_t)t * DIM;
    for (int d = lane; d < DIM; d += 32) {
        float xv = xr[d];
        const float4* g4 = reinterpret_cast<const float4*>(gw + (size_t)d * NE);
        float4 a = g4[0], b = g4[1];
        acc[0] += xv * a.x; acc[1] += xv * a.y; acc[2] += xv * a.z; acc[3] += xv * a.w;
        acc[4] += xv * b.x; acc[5] += xv * b.y; acc[6] += xv * b.z; acc[7] += xv * b.w;
    }
#pragma unroll
    for (int e = 0; e < NE; e++) acc[e] = warp_sum(acc[e]);
    if (lane == 0) {
        float lg[NE];
#pragma unroll
        for (int e = 0; e < NE; e++) lg[e] = (acc[e] + gb[e]) / TEMP;
        int i0 = 0;
#pragma unroll
        for (int e = 1; e < NE; e++) if (lg[e] > lg[i0]) i0 = e;
        int i1 = (i0 == 0) ? 1 : 0;
#pragma unroll
        for (int e = 0; e < NE; e++)
            if (e != i0 && lg[e] > lg[i1]) i1 = e;
        float ev = expf(lg[i1] - lg[i0]);
        float s = 1.f + ev;
        g_e0[t] = i0; g_e1[t] = i1;
        g_p0[t] = 1.f / s; g_p1[t] = ev / s;
        atomicAdd(&g_counts[i0], 1);
        atomicAdd(&g_counts[i1], 1);
    }
}

__global__ void prefix_kernel() {
    if (threadIdx.x == 0) {
        int s = 0;
        for (int e = 0; e < NE; e++) {
            g_poff[e] = s;
            s += ((g_counts[e] + 127) / 128) * 128;
            g_cursor[e] = 0;
        }
    }
}

__global__ void assign_kernel() {
    int t = blockIdx.x * 256 + threadIdx.x;
    if (t >= N_TOK) return;
    int e0 = g_e0[t], e1 = g_e1[t];
    int p = g_poff[e0] + atomicAdd(&g_cursor[e0], 1);
    g_rowtok[p] = t; g_pp0[t] = p;
    int q = g_poff[e1] + atomicAdd(&g_cursor[e1], 1);
    g_rowtok[q] = t; g_pp1[t] = q;
}

// gather + tf32-round selected token rows into padded per-expert slabs
__global__ void gather_kernel(const float* __restrict__ x) {
    int e  = blockIdx.y;
    int mt = blockIdx.x;
    int cnt = g_counts[e];
    if (mt * 128 >= cnt) return;
    int base = g_poff[e] + mt * 128;
    int tid = threadIdx.x;
    const float4* x4 = reinterpret_cast<const float4*>(x);
    float4* o4 = reinterpret_cast<float4*>(g_Xe);
#pragma unroll 4
    for (int i = 0; i < 128; i++) {
        if (mt * 128 + i < cnt) {
            int tok = g_rowtok[base + i];
            float4 v = x4[(size_t)tok * (DIM / 4) + tid];
            o4[(size_t)(base + i) * (DIM / 4) + tid] =
                make_float4(round_tf32(v.x), round_tf32(v.y), round_tf32(v.z), round_tf32(v.w));
        }
    }
}

// ---------------- tf32 mma.sync GEMM ----------------
// CTA tile 128x256, BK=32, 256 threads = 8 warps (2m x 4n), warp tile 64x64.
// A (g_Xe / g_H) is pre-rounded tf32; only B (fp32 weights) gets in-loop cvt.
#define A_STG (128 * 36)     // floats, row stride 36 (pad 4)
#define B_STG (32 * 264)     // floats, row stride 264 (pad 8)
#define SMEM_FFN_BYTES ((2 * A_STG + 2 * B_STG) * 4)

template<int K, int NF, bool GELU>
__global__ __launch_bounds__(256, 1)
void ffn_mma_kernel(const float* __restrict__ W,
                    const float* __restrict__ bias_in) {
    int e = blockIdx.z;
    int cnt = g_counts[e];
    int mt = blockIdx.y;
    if (mt * 128 >= cnt) return;
    int m0 = g_poff[e] + mt * 128;
    int n0 = blockIdx.x * 256;

    const float* Abase = (GELU ? g_Xe : g_H) + (size_t)m0 * K;
    const float* Bbase = W + (size_t)e * K * NF + n0;
    float* Cout = GELU ? g_H : g_Y;
    const float* bias = bias_in + (size_t)e * NF + n0;

    extern __shared__ float sm[];
    float* Asm = sm;
    float* Bsm = sm + 2 * A_STG;
    uint32_t sA32 = smem_u32(Asm), sB32 = smem_u32(Bsm);

    int tid = threadIdx.x, wid = tid >> 5, lane = tid & 31;
    int warp_m = wid & 1, warp_n = wid >> 1;
    int group = lane >> 2, tig = lane & 3;

    auto load_stage = [&](int kt, int s) {
        int k0 = kt * 32;
        uint32_t aD = sA32 + s * (A_STG * 4);
        uint32_t bD = sB32 + s * (B_STG * 4);
#pragma unroll
        for (int i = 0; i < 4; i++) {        // A: 128 rows x 8 x 16B
            int idx = tid + i * 256;
            int row = idx >> 3, c8 = idx & 7;
            cp_async16(aD + row * 144 + c8 * 16, Abase + (size_t)row * K + k0 + c8 * 4);
        }
#pragma unroll
        for (int i = 0; i < 8; i++) {        // B: 32 rows x 64 x 16B
            int idx = tid + i * 256;
            int kk = idx >> 6, c16 = idx & 63;
            cp_async16(bD + kk * 1056 + c16 * 16, Bbase + (size_t)(k0 + kk) * NF + c16 * 4);
        }
        asm volatile("cp.async.commit_group;");
    };

    float acc[4][8][4];
#pragma unroll
    for (int i = 0; i < 4; i++)
#pragma unroll
        for (int j = 0; j < 8; j++)
#pragma unroll
            for (int q = 0; q < 4; q++) acc[i][j][q] = 0.f;

    const int ktiles = K / 32;
    load_stage(0, 0);

    for (int kt = 0; kt < ktiles; kt++) {
        int s = kt & 1;
        if (kt + 1 < ktiles) {
            load_stage(kt + 1, s ^ 1);
            asm volatile("cp.async.wait_group 1;" ::: "memory");
        } else {
            asm volatile("cp.async.wait_group 0;" ::: "memory");
        }
        __syncthreads();

        const uint32_t* Ab = reinterpret_cast<const uint32_t*>(Asm + s * A_STG);
        const float*    Bb = Bsm + s * B_STG;
#pragma unroll
        for (int ks = 0; ks < 4; ks++) {
            int kb = ks * 8;
            uint32_t a[4][4], b[8][2];
#pragma unroll
            for (int m = 0; m < 4; m++) {
                int r = warp_m * 64 + m * 16 + group;
                a[m][0] = Ab[r * 36 + kb + tig];
                a[m][1] = Ab[(r + 8) * 36 + kb + tig];
                a[m][2] = Ab[r * 36 + kb + tig + 4];
                a[m][3] = Ab[(r + 8) * 36 + kb + tig + 4];
            }
#pragma unroll
            for (int n = 0; n < 8; n++) {
                int c = warp_n * 64 + n * 8 + group;
                b[n][0] = f2tf32(Bb[(kb + tig) * 264 + c]);
                b[n][1] = f2tf32(Bb[(kb + tig + 4) * 264 + c]);
            }
#pragma unroll
            for (int m = 0; m < 4; m++)
#pragma unroll
                for (int n = 0; n < 8; n++)
                    mma_tf32(acc[m][n], a[m], b[n]);
        }
        __syncthreads();
    }

    // epilogue: bias (+gelu) and store; GEMM1 output is tf32-rounded for GEMM2
#pragma unroll
    for (int m = 0; m < 4; m++) {
        int r0 = m0 + warp_m * 64 + m * 16 + group;
#pragma unroll
        for (int n = 0; n < 8; n++) {
            int c = warp_n * 64 + n * 8 + tig * 2;
            float bv0 = bias[c], bv1 = bias[c + 1];
#pragma unroll
            for (int h = 0; h < 2; h++) {
                float v0 = acc[m][n][h * 2 + 0] + bv0;
                float v1 = acc[m][n][h * 2 + 1] + bv1;
                if (GELU) {
                    v0 = 0.5f * v0 * (1.f + erff(v0 * 0.70710678118654752f));
                    v1 = 0.5f * v1 * (1.f + erff(v1 * 0.70710678118654752f));
                    v0 = round_tf32(v0);
                    v1 = round_tf32(v1);
                }
                *reinterpret_cast<float2*>(Cout + (size_t)(r0 + h * 8) * NF + n0 + c) =
                    make_float2(v0, v1);
            }
        }
    }
}

// ---------------- combine + LayerNorm ----------------
__global__ void ln_kernel(const float* __restrict__ ln_g,
                          const float* __restrict__ ln_b,
                          float* __restrict__ out) {
    int t = blockIdx.x;
    __shared__ float sv[DIM];
    __shared__ float rs[8], rq[8];
    int tid = threadIdx.x;
    float p0 = g_p0[t], p1 = g_p1[t];
    const float* ya = g_Y + (size_t)g_pp0[t] * DIM;
    const float* yb = g_Y + (size_t)g_pp1[t] * DIM;
    float lsum = 0.f, lsq = 0.f;
    for (int d = tid; d < DIM; d += 256) {
        float v = p0 * ya[d] + p1 * yb[d];
        sv[d] = v;
        lsum += v; lsq += v * v;
    }
    lsum = warp_sum(lsum); lsq = warp_sum(lsq);
    int lane = tid & 31, wid = tid >> 5;
    if (lane == 0) { rs[wid] = lsum; rq[wid] = lsq; }
    __syncthreads();
    if (tid == 0) {
        float s = 0.f, q = 0.f;
#pragma unroll
        for (int w = 0; w < 8; w++) { s += rs[w]; q += rq[w]; }
        rs[0] = s; rq[0] = q;
    }
    __syncthreads();
    float mu  = rs[0] / DIM;
    float var = rq[0] / DIM - mu * mu;
    float inv = rsqrtf(var + EPS);
    float* outr = out + (size_t)t * DIM;
    for (int d = tid; d < DIM; d += 256)
        outr[d] = (sv[d] - mu) * inv * ln_g[d] + ln_b[d];
}

// ---------------- launch ----------------
extern "C" void kernel_launch(void* const* d_in, const int* in_sizes, int n_in,
                              void* d_out, int out_size) {
    const float* x      = (const float*)d_in[0];
    const float* gate_w = (const float*)d_in[1];
    const float* gate_b = (const float*)d_in[2];
    const float* w1     = (const float*)d_in[3];
    const float* b1     = (const float*)d_in[4];
    const float* w2     = (const float*)d_in[5];
    const float* b2     = (const float*)d_in[6];
    const float* ln_g   = (const float*)d_in[7];
    const float* ln_b   = (const float*)d_in[8];
    float* out = (float*)d_out;

    cudaFuncSetAttribute(ffn_mma_kernel<DIM, FF, true>,
                         cudaFuncAttributeMaxDynamicSharedMemorySize, SMEM_FFN_BYTES);
    cudaFuncSetAttribute(ffn_mma_kernel<FF, DIM, false>,
                         cudaFuncAttributeMaxDynamicSharedMemorySize, SMEM_FFN_BYTES);

    zero_kernel<<<1, 32>>>();
    gate_kernel<<<N_TOK / 4, 128>>>(x, gate_w, gate_b);
    prefix_kernel<<<1, 32>>>();
    assign_kernel<<<N_TOK / 256, 256>>>();
    gather_kernel<<<dim3(32, NE), 256>>>(x);
    ffn_mma_kernel<DIM, FF, true ><<<dim3(FF / 256, 32, NE), 256, SMEM_FFN_BYTES>>>(w1, b1);
    ffn_mma_kernel<FF, DIM, false><<<dim3(DIM / 256, 32, NE), 256, SMEM_FFN_BYTES>>>(w2, b2);
    ln_kernel<<<N_TOK, 256>>>(ln_g, ln_b, out);
}